// round 2
// baseline (speedup 1.0000x reference)
#include <cuda_runtime.h>
#include <math.h>

#define NNODES 50000
#define FIN    256
#define HH     4
#define HD     64
#define F1     (HH*HD)          // 256
#define EMAX   1600000
#define EE_MAX (EMAX + NNODES)  // 1650000
#define SLOPE  0.2f

// ---------------- scratch (device globals; no allocation allowed) ----------
__device__ float g_h1[(size_t)NNODES * F1];     // 51.2 MB
__device__ float g_as1[NNODES * HH];
__device__ float g_ad1[NNODES * HH];
__device__ float g_den1[NNODES * HH];
__device__ float g_w1[(size_t)EE_MAX * HH];     // 26.4 MB
__device__ float g_o1[(size_t)NNODES * F1];     // 51.2 MB
__device__ float g_h2[(size_t)NNODES * HD];     // 12.8 MB
__device__ float g_as2[NNODES];
__device__ float g_ad2[NNODES];
__device__ float g_den2[NNODES];
__device__ float g_w2[EE_MAX];                  // 6.6 MB

// ---------------- vector global reductions (PTX 8.1+, sm_90+) --------------
__device__ __forceinline__ void redv4(float* p, float4 v) {
    asm volatile("red.global.add.v4.f32 [%0], {%1,%2,%3,%4};"
                 :: "l"(p), "f"(v.x), "f"(v.y), "f"(v.z), "f"(v.w) : "memory");
}
__device__ __forceinline__ void redv2(float* p, float2 v) {
    asm volatile("red.global.add.v2.f32 [%0], {%1,%2};"
                 :: "l"(p), "f"(v.x), "f"(v.y) : "memory");
}

// ---------------- SGEMM: C[M,N] = A[M,K] @ B[K,N], row-major ---------------
template<int BM, int BN, int BK, int TM, int TN>
__global__ void sgemm_kernel(const float* __restrict__ A,
                             const float* __restrict__ B,
                             float* __restrict__ C,
                             int M, int N, int K)
{
    __shared__ float As[BK][BM];
    __shared__ float Bs[BK][BN];
    constexpr int THREADS = (BM / TM) * (BN / TN);
    const int tid = threadIdx.x;
    const int tx  = tid % (BN / TN);
    const int ty  = tid / (BN / TN);
    const int row0 = blockIdx.y * BM;
    const int col0 = blockIdx.x * BN;

    float acc[TM][TN];
#pragma unroll
    for (int i = 0; i < TM; i++)
#pragma unroll
        for (int j = 0; j < TN; j++) acc[i][j] = 0.f;

    for (int k0 = 0; k0 < K; k0 += BK) {
#pragma unroll
        for (int i = tid; i < BM * BK / 4; i += THREADS) {
            int m  = i / (BK / 4);
            int kq = i % (BK / 4);
            float4 v = make_float4(0.f, 0.f, 0.f, 0.f);
            if (row0 + m < M)
                v = *(const float4*)&A[(size_t)(row0 + m) * K + k0 + kq * 4];
            As[kq * 4 + 0][m] = v.x;
            As[kq * 4 + 1][m] = v.y;
            As[kq * 4 + 2][m] = v.z;
            As[kq * 4 + 3][m] = v.w;
        }
#pragma unroll
        for (int i = tid; i < BK * BN / 4; i += THREADS) {
            int kk = i / (BN / 4);
            int nq = i % (BN / 4);
            *(float4*)&Bs[kk][nq * 4] =
                *(const float4*)&B[(size_t)(k0 + kk) * N + col0 + nq * 4];
        }
        __syncthreads();
#pragma unroll
        for (int k = 0; k < BK; k++) {
            float ra[TM], rb[TN];
#pragma unroll
            for (int i = 0; i < TM; i += 4) {
                float4 a = *(const float4*)&As[k][ty * TM + i];
                ra[i] = a.x; ra[i + 1] = a.y; ra[i + 2] = a.z; ra[i + 3] = a.w;
            }
#pragma unroll
            for (int j = 0; j < TN; j += 4) {
                float4 b = *(const float4*)&Bs[k][tx * TN + j];
                rb[j] = b.x; rb[j + 1] = b.y; rb[j + 2] = b.z; rb[j + 3] = b.w;
            }
#pragma unroll
            for (int i = 0; i < TM; i++)
#pragma unroll
                for (int j = 0; j < TN; j++)
                    acc[i][j] = fmaf(ra[i], rb[j], acc[i][j]);
        }
        __syncthreads();
    }
#pragma unroll
    for (int i = 0; i < TM; i++) {
        int m = row0 + ty * TM + i;
        if (m >= M) continue;
#pragma unroll
        for (int j = 0; j < TN; j += 4) {
            float4 v = make_float4(acc[i][j], acc[i][j + 1], acc[i][j + 2], acc[i][j + 3]);
            *(float4*)&C[(size_t)m * N + col0 + tx * TN + j] = v;
        }
    }
}

// ---------------- per-node attention logits: one warp per (node, head) -----
__global__ void alpha_kernel(const float* __restrict__ h,
                             const float* __restrict__ a_src,
                             const float* __restrict__ a_dst,
                             float* __restrict__ as_out,
                             float* __restrict__ ad_out,
                             int n_nodes, int heads)
{
    int gid  = blockIdx.x * blockDim.x + threadIdx.x;
    int warp = gid >> 5;
    int lane = gid & 31;
    int total = n_nodes * heads;
    if (warp >= total) return;
    int n  = warp / heads;
    int hd = warp % heads;
    const float* row = h + (size_t)n * heads * 64 + hd * 64;
    float x0 = row[lane], x1 = row[lane + 32];
    float s = x0 * a_src[hd * 64 + lane] + x1 * a_src[hd * 64 + lane + 32];
    float d = x0 * a_dst[hd * 64 + lane] + x1 * a_dst[hd * 64 + lane + 32];
#pragma unroll
    for (int o = 16; o > 0; o >>= 1) {
        s += __shfl_down_sync(0xffffffffu, s, o);
        d += __shfl_down_sync(0xffffffffu, d, o);
    }
    if (lane == 0) { as_out[warp] = s; ad_out[warp] = d; }
}

// ---------------- edge weights + denominator accumulation ------------------
// max-subtraction is skipped: softmax is shift-invariant and logits are small.
template<int HEADS>
__global__ void edge_w_kernel(const int* __restrict__ src,
                              const int* __restrict__ dst,
                              int E, int EE,
                              const float* __restrict__ as_in,
                              const float* __restrict__ ad_in,
                              float* __restrict__ w,
                              float* __restrict__ denom)
{
    int e = blockIdx.x * blockDim.x + threadIdx.x;
    if (e >= EE) return;
    int s, d;
    if (e < E) { s = src[e]; d = dst[e]; }
    else       { s = e - E; d = s; }
    if ((unsigned)s >= NNODES || (unsigned)d >= NNODES) return;  // defensive
    if (HEADS == 4) {
        float4 A = *(const float4*)(as_in + (size_t)s * 4);
        float4 B = *(const float4*)(ad_in + (size_t)d * 4);
        float e0 = A.x + B.x, e1 = A.y + B.y, e2 = A.z + B.z, e3 = A.w + B.w;
        e0 = e0 > 0.f ? e0 : SLOPE * e0;
        e1 = e1 > 0.f ? e1 : SLOPE * e1;
        e2 = e2 > 0.f ? e2 : SLOPE * e2;
        e3 = e3 > 0.f ? e3 : SLOPE * e3;
        float4 wv = make_float4(expf(e0), expf(e1), expf(e2), expf(e3));
        *(float4*)(w + (size_t)e * 4) = wv;
        atomicAdd(&denom[d * 4 + 0], wv.x);
        atomicAdd(&denom[d * 4 + 1], wv.y);
        atomicAdd(&denom[d * 4 + 2], wv.z);
        atomicAdd(&denom[d * 4 + 3], wv.w);
    } else {
        float ev = as_in[s] + ad_in[d];
        ev = ev > 0.f ? ev : SLOPE * ev;
        float wv = expf(ev);
        w[e] = wv;
        atomicAdd(&denom[d], wv);
    }
}

// ---------------- message aggregation: one warp per edge -------------------
template<int HEADS>
__global__ void aggregate_kernel(const int* __restrict__ src,
                                 const int* __restrict__ dst,
                                 int E, int EE,
                                 const float* __restrict__ w,
                                 const float* __restrict__ denom,
                                 const float* __restrict__ h,
                                 float* __restrict__ out)
{
    constexpr int F = HEADS * 64;
    int gid  = blockIdx.x * blockDim.x + threadIdx.x;
    int warp = gid >> 5;
    int lane = gid & 31;
    if (warp >= EE) return;
    int s, d;
    if (warp < E) { s = src[warp]; d = dst[warp]; }
    else          { s = warp - E; d = s; }
    if ((unsigned)s >= NNODES || (unsigned)d >= NNODES) return;  // defensive

    if (HEADS == 4) {
        float4 wv = *(const float4*)(w + (size_t)warp * 4);
        float4 dv = *(const float4*)(denom + (size_t)d * 4);
        float al0 = wv.x / (dv.x + 1e-16f);
        float al1 = wv.y / (dv.y + 1e-16f);
        float al2 = wv.z / (dv.z + 1e-16f);
        float al3 = wv.w / (dv.w + 1e-16f);
        int hidx = lane >> 3;            // 8 lanes per head (64 floats/head)
        float a = (hidx == 0) ? al0 : (hidx == 1) ? al1 : (hidx == 2) ? al2 : al3;
        const float4* hp = (const float4*)(h + (size_t)s * F + lane * 8);
        float4 v0 = hp[0], v1 = hp[1];
        v0.x *= a; v0.y *= a; v0.z *= a; v0.w *= a;
        v1.x *= a; v1.y *= a; v1.z *= a; v1.w *= a;
        float* op = out + (size_t)d * F + lane * 8;
        redv4(op, v0);
        redv4(op + 4, v1);
    } else {
        float a = w[warp] / (denom[d] + 1e-16f);
        float2 v = *(const float2*)(h + (size_t)s * 64 + lane * 2);
        v.x *= a; v.y *= a;
        redv2(out + (size_t)d * 64 + lane * 2, v);
    }
}

// ---------------- elementwise epilogues -------------------------------------
__global__ void bias_elu_kernel(float* __restrict__ o, const float* __restrict__ b,
                                int total)
{
    int i = blockIdx.x * blockDim.x + threadIdx.x;
    if (i >= total) return;
    float v = o[i] + b[i & (F1 - 1)];
    o[i] = v > 0.f ? v : expm1f(v);
}

__global__ void bias_add_kernel(float* __restrict__ o, const float* __restrict__ b,
                                int total)
{
    int i = blockIdx.x * blockDim.x + threadIdx.x;
    if (i >= total) return;
    o[i] += b[i & (HD - 1)];
}

// ---------------- launch ----------------------------------------------------
extern "C" void kernel_launch(void* const* d_in, const int* in_sizes, int n_in,
                              void* d_out, int out_size)
{
    const float* x     = (const float*)d_in[0];
    const int*   ei    = (const int*)d_in[1];     // JAX x64 disabled -> int32
    const float* W1    = (const float*)d_in[2];
    const float* asrc1 = (const float*)d_in[3];
    const float* adst1 = (const float*)d_in[4];
    const float* b1    = (const float*)d_in[5];
    const float* W2    = (const float*)d_in[6];
    const float* asrc2 = (const float*)d_in[7];
    const float* adst2 = (const float*)d_in[8];
    const float* b2    = (const float*)d_in[9];
    float*       out   = (float*)d_out;

    int E = in_sizes[1] / 2;
    if (E > EMAX) E = EMAX;
    int EE = E + NNODES;
    const int* src = ei;
    const int* dst = ei + E;

    float *h1, *as1, *ad1, *den1, *w1, *o1, *h2, *as2, *ad2, *den2, *w2;
    cudaGetSymbolAddress((void**)&h1,   g_h1);
    cudaGetSymbolAddress((void**)&as1,  g_as1);
    cudaGetSymbolAddress((void**)&ad1,  g_ad1);
    cudaGetSymbolAddress((void**)&den1, g_den1);
    cudaGetSymbolAddress((void**)&w1,   g_w1);
    cudaGetSymbolAddress((void**)&o1,   g_o1);
    cudaGetSymbolAddress((void**)&h2,   g_h2);
    cudaGetSymbolAddress((void**)&as2,  g_as2);
    cudaGetSymbolAddress((void**)&ad2,  g_ad2);
    cudaGetSymbolAddress((void**)&den2, g_den2);
    cudaGetSymbolAddress((void**)&w2,   g_w2);

    cudaMemsetAsync(den1, 0, (size_t)NNODES * HH * sizeof(float));
    cudaMemsetAsync(o1,   0, (size_t)NNODES * F1 * sizeof(float));
    cudaMemsetAsync(den2, 0, (size_t)NNODES * sizeof(float));
    cudaMemsetAsync(out,  0, (size_t)out_size * sizeof(float));

    // ---- layer 1 ----
    {
        dim3 grid(F1 / 128, (NNODES + 127) / 128);
        sgemm_kernel<128, 128, 16, 8, 8><<<grid, 256>>>(x, W1, h1, NNODES, F1, FIN);
    }
    {
        int warps = NNODES * HH;
        alpha_kernel<<<(warps + 7) / 8, 256>>>(h1, asrc1, adst1, as1, ad1, NNODES, HH);
    }
    edge_w_kernel<4><<<(EE + 255) / 256, 256>>>(src, dst, E, EE, as1, ad1, w1, den1);
    aggregate_kernel<4><<<(EE + 7) / 8, 256>>>(src, dst, E, EE, w1, den1, h1, o1);
    bias_elu_kernel<<<(NNODES * F1 + 255) / 256, 256>>>(o1, b1, NNODES * F1);

    // ---- layer 2 ----
    {
        dim3 grid(1, (NNODES + 127) / 128);
        sgemm_kernel<128, 64, 16, 8, 4><<<grid, 256>>>(o1, W2, h2, NNODES, HD, F1);
    }
    alpha_kernel<<<(NNODES + 7) / 8, 256>>>(h2, asrc2, adst2, as2, ad2, NNODES, 1);
    edge_w_kernel<1><<<(EE + 255) / 256, 256>>>(src, dst, E, EE, as2, ad2, w2, den2);
    aggregate_kernel<1><<<(EE + 7) / 8, 256>>>(src, dst, E, EE, w2, den2, h2, out);
    bias_add_kernel<<<(NNODES * HD + 255) / 256, 256>>>(out, b2, NNODES * HD);
}

// round 3
// speedup vs baseline: 1.8616x; 1.8616x over previous
#include <cuda_runtime.h>
#include <math.h>

#define NNODES 50000
#define FIN    256
#define HH     4
#define HD     64
#define F1     (HH*HD)          // 256
#define EMAX   1600000
#define SLOPE  0.2f
#define FULLM  0xffffffffu

// ---------------- scratch (device globals) ----------------------------------
__device__ float g_h1[(size_t)NNODES * F1];     // 51.2 MB
__device__ float g_o1[(size_t)NNODES * F1];     // 51.2 MB
__device__ float g_h2[(size_t)NNODES * HD];     // 12.8 MB
__device__ float g_as1[NNODES * HH];
__device__ float g_ad1[NNODES * HH];
__device__ float g_as2[NNODES];
__device__ float g_ad2[NNODES];
__device__ int   g_deg[NNODES];
__device__ int   g_fill[NNODES];
__device__ int   g_roff[NNODES + 1];
__device__ int   g_csr_src[EMAX];               // 6.4 MB

// ---------------- SGEMM: C[M,N] = A[M,K] @ B[K,N], row-major ---------------
template<int BM, int BN, int BK, int TM, int TN>
__global__ void sgemm_kernel(const float* __restrict__ A,
                             const float* __restrict__ B,
                             float* __restrict__ C,
                             int M, int N, int K)
{
    __shared__ float As[BK][BM];
    __shared__ float Bs[BK][BN];
    constexpr int THREADS = (BM / TM) * (BN / TN);
    const int tid = threadIdx.x;
    const int tx  = tid % (BN / TN);
    const int ty  = tid / (BN / TN);
    const int row0 = blockIdx.y * BM;
    const int col0 = blockIdx.x * BN;

    float acc[TM][TN];
#pragma unroll
    for (int i = 0; i < TM; i++)
#pragma unroll
        for (int j = 0; j < TN; j++) acc[i][j] = 0.f;

    for (int k0 = 0; k0 < K; k0 += BK) {
#pragma unroll
        for (int i = tid; i < BM * BK / 4; i += THREADS) {
            int m  = i / (BK / 4);
            int kq = i % (BK / 4);
            float4 v = make_float4(0.f, 0.f, 0.f, 0.f);
            if (row0 + m < M)
                v = *(const float4*)&A[(size_t)(row0 + m) * K + k0 + kq * 4];
            As[kq * 4 + 0][m] = v.x;
            As[kq * 4 + 1][m] = v.y;
            As[kq * 4 + 2][m] = v.z;
            As[kq * 4 + 3][m] = v.w;
        }
#pragma unroll
        for (int i = tid; i < BK * BN / 4; i += THREADS) {
            int kk = i / (BN / 4);
            int nq = i % (BN / 4);
            *(float4*)&Bs[kk][nq * 4] =
                *(const float4*)&B[(size_t)(k0 + kk) * N + col0 + nq * 4];
        }
        __syncthreads();
#pragma unroll
        for (int k = 0; k < BK; k++) {
            float ra[TM], rb[TN];
#pragma unroll
            for (int i = 0; i < TM; i += 4) {
                float4 a = *(const float4*)&As[k][ty * TM + i];
                ra[i] = a.x; ra[i + 1] = a.y; ra[i + 2] = a.z; ra[i + 3] = a.w;
            }
#pragma unroll
            for (int j = 0; j < TN; j += 4) {
                float4 b = *(const float4*)&Bs[k][tx * TN + j];
                rb[j] = b.x; rb[j + 1] = b.y; rb[j + 2] = b.z; rb[j + 3] = b.w;
            }
#pragma unroll
            for (int i = 0; i < TM; i++)
#pragma unroll
                for (int j = 0; j < TN; j++)
                    acc[i][j] = fmaf(ra[i], rb[j], acc[i][j]);
        }
        __syncthreads();
    }
#pragma unroll
    for (int i = 0; i < TM; i++) {
        int m = row0 + ty * TM + i;
        if (m >= M) continue;
#pragma unroll
        for (int j = 0; j < TN; j += 4) {
            float4 v = make_float4(acc[i][j], acc[i][j + 1], acc[i][j + 2], acc[i][j + 3]);
            *(float4*)&C[(size_t)m * N + col0 + tx * TN + j] = v;
        }
    }
}

// ---------------- CSR build -------------------------------------------------
__global__ void hist_kernel(const int* __restrict__ dst, int E, int* __restrict__ deg)
{
    int e = blockIdx.x * blockDim.x + threadIdx.x;
    if (e >= E) return;
    int d = dst[e];
    if ((unsigned)d < NNODES) atomicAdd(&deg[d], 1);
}

__global__ void scan_kernel(const int* __restrict__ deg, int* __restrict__ roff)
{
    __shared__ int part[1024];
    const int tid = threadIdx.x;
    const int CH = (NNODES + 1023) / 1024;
    const int base = tid * CH;
    int s = 0;
    for (int i = 0; i < CH; i++) {
        int idx = base + i;
        if (idx < NNODES) s += deg[idx];
    }
    part[tid] = s;
    __syncthreads();
    for (int off = 1; off < 1024; off <<= 1) {
        int v = 0;
        if (tid >= off) v = part[tid - off];
        __syncthreads();
        if (tid >= off) part[tid] += v;
        __syncthreads();
    }
    int run = (tid == 0) ? 0 : part[tid - 1];
    for (int i = 0; i < CH; i++) {
        int idx = base + i;
        if (idx < NNODES) { roff[idx] = run; run += deg[idx]; }
    }
    if (tid == 1023) roff[NNODES] = run;
}

__global__ void scatter_kernel(const int* __restrict__ src, const int* __restrict__ dst,
                               int E, const int* __restrict__ roff,
                               int* __restrict__ fill, int* __restrict__ csr)
{
    int e = blockIdx.x * blockDim.x + threadIdx.x;
    if (e >= E) return;
    int d = dst[e], s = src[e];
    if ((unsigned)d >= NNODES || (unsigned)s >= NNODES) return;
    int p = atomicAdd(&fill[d], 1);
    csr[roff[d] + p] = s;
}

// ---------------- per-node attention logits: one warp per (node, head) -----
__global__ void alpha_kernel(const float* __restrict__ h,
                             const float* __restrict__ a_src,
                             const float* __restrict__ a_dst,
                             float* __restrict__ as_out,
                             float* __restrict__ ad_out,
                             int n_nodes, int heads)
{
    int gid  = blockIdx.x * blockDim.x + threadIdx.x;
    int warp = gid >> 5;
    int lane = gid & 31;
    int total = n_nodes * heads;
    if (warp >= total) return;
    int n  = warp / heads;
    int hd = warp % heads;
    const float* row = h + (size_t)n * heads * 64 + hd * 64;
    float x0 = row[lane], x1 = row[lane + 32];
    float s = x0 * a_src[hd * 64 + lane] + x1 * a_src[hd * 64 + lane + 32];
    float d = x0 * a_dst[hd * 64 + lane] + x1 * a_dst[hd * 64 + lane + 32];
#pragma unroll
    for (int o = 16; o > 0; o >>= 1) {
        s += __shfl_down_sync(FULLM, s, o);
        d += __shfl_down_sync(FULLM, d, o);
    }
    if (lane == 0) { as_out[warp] = s; ad_out[warp] = d; }
}

__device__ __forceinline__ float lexp(float e) {
    e = e > 0.f ? e : SLOPE * e;
    return __expf(e);
}

// ---------------- layer-1 fused softmax + gather aggregation ----------------
// one warp per destination node; self-loop handled inline; bias+ELU epilogue.
__global__ void gather1_kernel(const int* __restrict__ roff,
                               const int* __restrict__ csr,
                               const float* __restrict__ as_in,
                               const float* __restrict__ ad_in,
                               const float* __restrict__ h,
                               const float* __restrict__ bias,
                               float* __restrict__ out)
{
    int warp = (blockIdx.x * blockDim.x + threadIdx.x) >> 5;
    int lane = threadIdx.x & 31;
    if (warp >= NNODES) return;
    const int d = warp;
    const int beg = roff[d], end = roff[d + 1];

    float4 ad4 = *(const float4*)(ad_in + (size_t)d * 4);

    // ---- pass 1: softmax denominator, lanes parallel over edges ----
    float4 ws = make_float4(0.f, 0.f, 0.f, 0.f);
    for (int j = beg + lane; j < end; j += 32) {
        int s = csr[j];
        float4 a = *(const float4*)(as_in + (size_t)s * 4);
        ws.x += lexp(a.x + ad4.x);
        ws.y += lexp(a.y + ad4.y);
        ws.z += lexp(a.z + ad4.z);
        ws.w += lexp(a.w + ad4.w);
    }
    if (lane == 0) {  // self loop
        float4 a = *(const float4*)(as_in + (size_t)d * 4);
        ws.x += lexp(a.x + ad4.x);
        ws.y += lexp(a.y + ad4.y);
        ws.z += lexp(a.z + ad4.z);
        ws.w += lexp(a.w + ad4.w);
    }
#pragma unroll
    for (int o = 16; o > 0; o >>= 1) {
        ws.x += __shfl_xor_sync(FULLM, ws.x, o);
        ws.y += __shfl_xor_sync(FULLM, ws.y, o);
        ws.z += __shfl_xor_sync(FULLM, ws.z, o);
        ws.w += __shfl_xor_sync(FULLM, ws.w, o);
    }
    const int hidx = lane >> 3;  // 8 lanes per head
    float wsum = (hidx == 0) ? ws.x : (hidx == 1) ? ws.y : (hidx == 2) ? ws.z : ws.w;
    float inv  = 1.f / (wsum + 1e-16f);
    float adh  = (hidx == 0) ? ad4.x : (hidx == 1) ? ad4.y : (hidx == 2) ? ad4.z : ad4.w;

    // ---- pass 2: weighted gather into registers ----
    float acc[8];
#pragma unroll
    for (int k = 0; k < 8; k++) acc[k] = 0.f;

    for (int j0 = beg; j0 < end; j0 += 32) {
        int cnt = min(32, end - j0);
        int my = (lane < cnt) ? csr[j0 + lane] : 0;
        int t = 0;
        for (; t + 1 < cnt; t += 2) {
            int s0 = __shfl_sync(FULLM, my, t);
            int s1 = __shfl_sync(FULLM, my, t + 1);
            float w0 = lexp(as_in[(size_t)s0 * 4 + hidx] + adh);
            float w1 = lexp(as_in[(size_t)s1 * 4 + hidx] + adh);
            const float4* p0 = (const float4*)(h + (size_t)s0 * F1 + lane * 8);
            const float4* p1 = (const float4*)(h + (size_t)s1 * F1 + lane * 8);
            float4 u0 = p0[0], u1 = p0[1];
            float4 v0 = p1[0], v1 = p1[1];
            acc[0] = fmaf(w0, u0.x, acc[0]); acc[1] = fmaf(w0, u0.y, acc[1]);
            acc[2] = fmaf(w0, u0.z, acc[2]); acc[3] = fmaf(w0, u0.w, acc[3]);
            acc[4] = fmaf(w0, u1.x, acc[4]); acc[5] = fmaf(w0, u1.y, acc[5]);
            acc[6] = fmaf(w0, u1.z, acc[6]); acc[7] = fmaf(w0, u1.w, acc[7]);
            acc[0] = fmaf(w1, v0.x, acc[0]); acc[1] = fmaf(w1, v0.y, acc[1]);
            acc[2] = fmaf(w1, v0.z, acc[2]); acc[3] = fmaf(w1, v0.w, acc[3]);
            acc[4] = fmaf(w1, v1.x, acc[4]); acc[5] = fmaf(w1, v1.y, acc[5]);
            acc[6] = fmaf(w1, v1.z, acc[6]); acc[7] = fmaf(w1, v1.w, acc[7]);
        }
        if (t < cnt) {
            int s0 = __shfl_sync(FULLM, my, t);
            float w0 = lexp(as_in[(size_t)s0 * 4 + hidx] + adh);
            const float4* p0 = (const float4*)(h + (size_t)s0 * F1 + lane * 8);
            float4 u0 = p0[0], u1 = p0[1];
            acc[0] = fmaf(w0, u0.x, acc[0]); acc[1] = fmaf(w0, u0.y, acc[1]);
            acc[2] = fmaf(w0, u0.z, acc[2]); acc[3] = fmaf(w0, u0.w, acc[3]);
            acc[4] = fmaf(w0, u1.x, acc[4]); acc[5] = fmaf(w0, u1.y, acc[5]);
            acc[6] = fmaf(w0, u1.z, acc[6]); acc[7] = fmaf(w0, u1.w, acc[7]);
        }
    }
    {   // self loop
        float w0 = lexp(as_in[(size_t)d * 4 + hidx] + adh);
        const float4* p0 = (const float4*)(h + (size_t)d * F1 + lane * 8);
        float4 u0 = p0[0], u1 = p0[1];
        acc[0] = fmaf(w0, u0.x, acc[0]); acc[1] = fmaf(w0, u0.y, acc[1]);
        acc[2] = fmaf(w0, u0.z, acc[2]); acc[3] = fmaf(w0, u0.w, acc[3]);
        acc[4] = fmaf(w0, u1.x, acc[4]); acc[5] = fmaf(w0, u1.y, acc[5]);
        acc[6] = fmaf(w0, u1.z, acc[6]); acc[7] = fmaf(w0, u1.w, acc[7]);
    }

    // ---- epilogue: normalize + bias + ELU ----
    size_t base = (size_t)d * F1 + lane * 8;
#pragma unroll
    for (int k = 0; k < 8; k++) {
        float v = acc[k] * inv + bias[lane * 8 + k];
        out[base + k] = v > 0.f ? v : expm1f(v);
    }
}

// ---------------- layer-2 fused softmax + gather aggregation ----------------
__global__ void gather2_kernel(const int* __restrict__ roff,
                               const int* __restrict__ csr,
                               const float* __restrict__ as_in,
                               const float* __restrict__ ad_in,
                               const float* __restrict__ h,
                               const float* __restrict__ bias,
                               float* __restrict__ out)
{
    int warp = (blockIdx.x * blockDim.x + threadIdx.x) >> 5;
    int lane = threadIdx.x & 31;
    if (warp >= NNODES) return;
    const int d = warp;
    const int beg = roff[d], end = roff[d + 1];

    float add = ad_in[d];

    float ws = 0.f;
    for (int j = beg + lane; j < end; j += 32) {
        int s = csr[j];
        ws += lexp(as_in[s] + add);
    }
    if (lane == 0) ws += lexp(as_in[d] + add);
#pragma unroll
    for (int o = 16; o > 0; o >>= 1) ws += __shfl_xor_sync(FULLM, ws, o);
    float inv = 1.f / (ws + 1e-16f);

    float2 acc = make_float2(0.f, 0.f);
    for (int j0 = beg; j0 < end; j0 += 32) {
        int cnt = min(32, end - j0);
        int my = (lane < cnt) ? csr[j0 + lane] : 0;
        int t = 0;
        for (; t + 1 < cnt; t += 2) {
            int s0 = __shfl_sync(FULLM, my, t);
            int s1 = __shfl_sync(FULLM, my, t + 1);
            float w0 = lexp(as_in[s0] + add);
            float w1 = lexp(as_in[s1] + add);
            float2 u = *(const float2*)(h + (size_t)s0 * HD + lane * 2);
            float2 v = *(const float2*)(h + (size_t)s1 * HD + lane * 2);
            acc.x = fmaf(w0, u.x, acc.x); acc.y = fmaf(w0, u.y, acc.y);
            acc.x = fmaf(w1, v.x, acc.x); acc.y = fmaf(w1, v.y, acc.y);
        }
        if (t < cnt) {
            int s0 = __shfl_sync(FULLM, my, t);
            float w0 = lexp(as_in[s0] + add);
            float2 u = *(const float2*)(h + (size_t)s0 * HD + lane * 2);
            acc.x = fmaf(w0, u.x, acc.x); acc.y = fmaf(w0, u.y, acc.y);
        }
    }
    {   // self loop
        float w0 = lexp(as_in[d] + add);
        float2 u = *(const float2*)(h + (size_t)d * HD + lane * 2);
        acc.x = fmaf(w0, u.x, acc.x); acc.y = fmaf(w0, u.y, acc.y);
    }

    out[(size_t)d * HD + lane * 2 + 0] = acc.x * inv + bias[lane * 2 + 0];
    out[(size_t)d * HD + lane * 2 + 1] = acc.y * inv + bias[lane * 2 + 1];
}

// ---------------- launch ----------------------------------------------------
extern "C" void kernel_launch(void* const* d_in, const int* in_sizes, int n_in,
                              void* d_out, int out_size)
{
    const float* x     = (const float*)d_in[0];
    const int*   ei    = (const int*)d_in[1];     // int32 (JAX x64 disabled)
    const float* W1    = (const float*)d_in[2];
    const float* asrc1 = (const float*)d_in[3];
    const float* adst1 = (const float*)d_in[4];
    const float* b1    = (const float*)d_in[5];
    const float* W2    = (const float*)d_in[6];
    const float* asrc2 = (const float*)d_in[7];
    const float* adst2 = (const float*)d_in[8];
    const float* b2    = (const float*)d_in[9];
    float*       out   = (float*)d_out;

    int E = in_sizes[1] / 2;
    if (E > EMAX) E = EMAX;
    const int* src = ei;
    const int* dst = ei + E;

    float *h1, *o1, *h2, *as1, *ad1, *as2, *ad2;
    int *deg, *fill, *roff, *csr;
    cudaGetSymbolAddress((void**)&h1,   g_h1);
    cudaGetSymbolAddress((void**)&o1,   g_o1);
    cudaGetSymbolAddress((void**)&h2,   g_h2);
    cudaGetSymbolAddress((void**)&as1,  g_as1);
    cudaGetSymbolAddress((void**)&ad1,  g_ad1);
    cudaGetSymbolAddress((void**)&as2,  g_as2);
    cudaGetSymbolAddress((void**)&ad2,  g_ad2);
    cudaGetSymbolAddress((void**)&deg,  g_deg);
    cudaGetSymbolAddress((void**)&fill, g_fill);
    cudaGetSymbolAddress((void**)&roff, g_roff);
    cudaGetSymbolAddress((void**)&csr,  g_csr_src);

    // ---- CSR build (reused by both layers) ----
    cudaMemsetAsync(deg,  0, NNODES * sizeof(int));
    cudaMemsetAsync(fill, 0, NNODES * sizeof(int));
    hist_kernel<<<(E + 255) / 256, 256>>>(dst, E, deg);
    scan_kernel<<<1, 1024>>>(deg, roff);
    scatter_kernel<<<(E + 255) / 256, 256>>>(src, dst, E, roff, fill, csr);

    // ---- layer 1 ----
    {
        dim3 grid(F1 / 128, (NNODES + 127) / 128);
        sgemm_kernel<128, 128, 16, 8, 8><<<grid, 256>>>(x, W1, h1, NNODES, F1, FIN);
    }
    alpha_kernel<<<(NNODES * HH + 7) / 8, 256>>>(h1, asrc1, adst1, as1, ad1, NNODES, HH);
    gather1_kernel<<<(NNODES + 7) / 8, 256>>>(roff, csr, as1, ad1, h1, b1, o1);

    // ---- layer 2 ----
    {
        dim3 grid(1, (NNODES + 127) / 128);
        sgemm_kernel<128, 64, 16, 8, 4><<<grid, 256>>>(o1, W2, h2, NNODES, HD, F1);
    }
    alpha_kernel<<<(NNODES + 7) / 8, 256>>>(h2, asrc2, adst2, as2, ad2, NNODES, 1);
    gather2_kernel<<<(NNODES + 7) / 8, 256>>>(roff, csr, as2, ad2, h2, b2, out);
}